// round 17
// baseline (speedup 1.0000x reference)
#include <cuda_runtime.h>
#include <cuda_bf16.h>
#include <math.h>
#include <stdint.h>

#define Bsz   32
#define Mrows 65536
#define Wc    64
#define Kk    8
#define Rr    9
#define INF_  512
#define IFACE 138
#define NBLK  64                       // distance blocks per batch
#define ROWS_PER_BLK (Mrows / NBLK)    // 1024
#define NSTG  16                       // stages per block (64 rows each)
#define STG_BYTES 16384                // 64 rows * 256 B
#define ULLMAX 0xFFFFFFFFFFFFFFFFull

// Output layout: gathered[:, :8, :] (32*8*64) | read_weights_new (32*1*9) | gathered (32*9*64)
#define OUT0_OFF 0
#define OUT1_OFF 16384
#define OUT2_OFF 16672

typedef unsigned long long u64;

// ---------------- device scratch (no allocation allowed) ----------------
__device__ __align__(16) float g_q[Bsz * Wc];          // read_query per batch
__device__ __align__(16) float g_rv[Bsz * Rr * Wc];    // updated read vectors
__device__ float              g_drv[Bsz * Rr];         // ||rv - q||^2
__device__ int                g_flag[Mrows];           // scattered pos -> k (valid only where mask bit set)
__device__ unsigned           g_mask[Mrows / 32];      // per-(block,group) bitmask (8 KB)
__device__ u64                g_cand[Bsz * NBLK * Kk]; // phase-A candidates
__device__ unsigned           g_cnt[Bsz];              // per-batch done counters (reset each replay)

// Mask addressing: for row m,  word = (m>>10)*32 + (m&31),  bit = (m>>5)&31.

// ---------------- packed f32x2 helpers (PTX-only; ptxas won't auto-fuse) ----------------
__device__ __forceinline__ u64 pack2(float lo, float hi) {
    u64 r; asm("mov.b64 %0,{%1,%2};" : "=l"(r) : "f"(lo), "f"(hi)); return r;
}
__device__ __forceinline__ void unpack2(u64 v, float& lo, float& hi) {
    asm("mov.b64 {%0,%1},%2;" : "=f"(lo), "=f"(hi) : "l"(v));
}
__device__ __forceinline__ u64 addx2(u64 a, u64 b) {
    u64 r; asm("add.rn.f32x2 %0,%1,%2;" : "=l"(r) : "l"(a), "l"(b)); return r;
}
__device__ __forceinline__ u64 mulx2(u64 a, u64 b) {
    u64 r; asm("mul.rn.f32x2 %0,%1,%2;" : "=l"(r) : "l"(a), "l"(b)); return r;
}
__device__ __forceinline__ u64 fmax2(u64 a, u64 b, u64 c) {
    u64 r; asm("fma.rn.f32x2 %0,%1,%2,%3;" : "=l"(r) : "l"(a), "l"(b), "l"(c)); return r;
}

// ---------------- K1: fused setup ----------------
__global__ __launch_bounds__(256) void k_setup(
    const float* __restrict__ xi, const float* __restrict__ W,
    const float* __restrict__ bias, const float* __restrict__ read_weights,
    const float* __restrict__ read_vectors, const int* __restrict__ read_positions)
{
    int b = blockIdx.x, t = threadIdx.x;

    if (b == Bsz) {
        __shared__ int s_pos[Bsz * Rr];
        #pragma unroll
        for (int i = 0; i < 8; i++) g_mask[t + i * 256] = 0u;
        if (t < Bsz) g_cnt[t] = 0u;
        for (int i = t; i < Bsz * Rr; i += 256) s_pos[i] = read_positions[i];
        __syncthreads();
        for (int j = t; j < Bsz * Rr; j += 256) {
            int p = s_pos[j];
            bool win = true;
            for (int j2 = j + 1; j2 < Bsz * Rr; j2++)
                if (s_pos[j2] == p) { win = false; break; }
            if (win) {
                g_flag[p] = j % Rr;
                atomicOr(&g_mask[(p >> 10) * 32 + (p & 31)], 1u << ((p >> 5) & 31));
            }
        }
        return;
    }

    __shared__ float s_xi[INF_];
    __shared__ float s_if[IFACE];
    __shared__ float s_ww[Rr];
    __shared__ float s_rv[Rr * Wc];

    for (int i = t; i < INF_; i += 256) s_xi[i] = xi[b * INF_ + i];
    __syncthreads();

    if (t < IFACE) {
        float a0 = 0.f, a1 = 0.f, a2 = 0.f, a3 = 0.f;
        #pragma unroll 2
        for (int i = 0; i < INF_; i += 8) {
            a0 = fmaf(s_xi[i + 0], W[(i + 0) * IFACE + t], a0);
            a1 = fmaf(s_xi[i + 1], W[(i + 1) * IFACE + t], a1);
            a2 = fmaf(s_xi[i + 2], W[(i + 2) * IFACE + t], a2);
            a3 = fmaf(s_xi[i + 3], W[(i + 3) * IFACE + t], a3);
            a0 = fmaf(s_xi[i + 4], W[(i + 4) * IFACE + t], a0);
            a1 = fmaf(s_xi[i + 5], W[(i + 5) * IFACE + t], a1);
            a2 = fmaf(s_xi[i + 6], W[(i + 6) * IFACE + t], a2);
            a3 = fmaf(s_xi[i + 7], W[(i + 7) * IFACE + t], a3);
        }
        s_if[t] = (a0 + a1) + (a2 + a3) + bias[t];
    }
    __syncthreads();

    if (t < Wc) g_q[b * Wc + t] = s_if[t];
    if (t < Rr) {
        float gate = 1.0f / (1.0f + expf(-s_if[IFACE - 1]));
        float ig   = s_if[2 * Wc + t];
        float rw   = read_weights[b * Rr + t];
        s_ww[t] = gate * (ig * rw + (1.0f - ig));
    }
    __syncthreads();

    for (int i = t; i < Rr * Wc; i += 256) {
        int r = i >> 6, w = i & 63;
        float v = read_vectors[b * Rr * Wc + i] + s_ww[r] * s_if[Wc + w];
        s_rv[i] = v;
        g_rv[b * Rr * Wc + i] = v;
    }
    __syncthreads();

    if (t < Rr) {
        float acc = 0.0f;
        for (int w = 0; w < Wc; w++) {
            float d = s_rv[t * Wc + w] - s_if[w];
            acc = fmaf(d, d, acc);
        }
        g_drv[b * Rr + t] = acc;
    }
}

// ---------------- distance for one row (8 lanes x 32B), packed f32x2 ----------------
__device__ __forceinline__ float row_dist(longlong2 r0, longlong2 r1,
                                          u64 nq0, u64 nq1, u64 nq2, u64 nq3) {
    u64 d0 = addx2((u64)r0.x, nq0);
    u64 d1 = addx2((u64)r0.y, nq1);
    u64 d2 = addx2((u64)r1.x, nq2);
    u64 d3 = addx2((u64)r1.y, nq3);
    u64 acc = mulx2(d0, d0);
    acc = fmax2(d1, d1, acc);
    acc = fmax2(d2, d2, acc);
    acc = fmax2(d3, d3, acc);
    float lo, hi; unpack2(acc, lo, hi);
    float s = lo + hi;
    s += __shfl_xor_sync(0xffffffffu, s, 4, 8);
    s += __shfl_xor_sync(0xffffffffu, s, 2, 8);
    s += __shfl_xor_sync(0xffffffffu, s, 1, 8);
    return s;
}

__device__ __forceinline__ void insert_cand(u64* best, u64 cand) {
    if (cand < best[7]) {
        best[7] = cand;
        #pragma unroll
        for (int i = 7; i >= 1; i--) {
            if (best[i] < best[i - 1]) {
                u64 tmp = best[i - 1]; best[i - 1] = best[i]; best[i] = tmp;
            }
        }
    }
}

// cp.async: 4x16B (2 rows x 32B for this thread) into stage st, then commit.
// smem layout is phase-interleaved for conflict-free LDS.128:
//   slot(t, chunk) = (t>>3)*512 + chunk*128 + (t&7)*16
#define PIPE_ISSUE(s_, st_) do {                                              \
    unsigned int d_ = sb + (st_) * STG_BYTES;                                 \
    const char* src_ = gp + (s_) * STG_BYTES;                                 \
    asm volatile(                                                             \
        "cp.async.cg.shared.global [%0], [%4], 16;\n\t"                       \
        "cp.async.cg.shared.global [%1], [%5], 16;\n\t"                       \
        "cp.async.cg.shared.global [%2], [%6], 16;\n\t"                       \
        "cp.async.cg.shared.global [%3], [%7], 16;\n\t"                       \
        "cp.async.commit_group;"                                              \
        :: "r"(d_), "r"(d_ + 128), "r"(d_ + 256), "r"(d_ + 384),              \
           "l"(src_), "l"(src_ + 16), "l"(src_ + 8192), "l"(src_ + 8208)      \
        : "memory");                                                          \
} while (0)

// ---------------- K2: cp.async 3-stage pipelined streaming distance ----------------
// R11 compute (8 lanes/row, distributed top-8, float-threshold fast path);
// loads fully decoupled via per-thread cp.async into smem (no hot-loop barriers).
extern "C" __global__ __launch_bounds__(256) void k_dist(
    const float* __restrict__ sparse, const int* __restrict__ last_used,
    float* __restrict__ out)
{
    extern __shared__ char dynsmem[];

    const int b    = blockIdx.y;
    const int t    = threadIdx.x;
    const int lane = t & 31, warp = t >> 5;
    const int lir  = lane & 7;                 // lane-in-row (8 lanes x 32B = 256B row)
    const int G    = warp * 4 + (lane >> 3);   // group slot 0..31
    const int row0 = blockIdx.x * ROWS_PER_BLK;
    const unsigned gmask = 0xFFu << (lane & 24);   // member mask of this 8-lane group

    // my smem base (u32 shared-window address), phase-interleaved slot
    unsigned int sb;
    {
        unsigned int s0;
        asm("{ .reg .u64 tmp; cvta.to.shared.u64 tmp, %1; cvt.u32.u64 %0, tmp; }"
            : "=r"(s0) : "l"(dynsmem));
        sb = s0 + (unsigned int)((t >> 3) * 512 + (t & 7) * 16);
    }
    const char* my_smem = dynsmem + ((t >> 3) * 512 + (t & 7) * 16);

    // my global base: stage s covers rows [row0 + s*64, +64); my rows: +G and +G+32
    const char* gp = (const char*)(sparse + ((size_t)b * Mrows + row0 + G) * Wc) + lir * 32;

    const float4* qp = (const float4*)(g_q + b * Wc + lir * 8);
    float4 qa = qp[0], qb = qp[1];
    u64 nq0 = pack2(-qa.x, -qa.y), nq1 = pack2(-qa.z, -qa.w);
    u64 nq2 = pack2(-qb.x, -qb.y), nq3 = pack2(-qb.z, -qb.w);

    const unsigned mk = g_mask[blockIdx.x * 32 + G];   // same word in all 8 lanes of group

    u64 v = ULLMAX;            // my rank-lir candidate (sorted asc across group)
    u64 thresh = ULLMAX;       // rank-7 value (uniform in group)
    float tf = __uint_as_float((unsigned)(thresh >> 32));  // NaN -> !(s>tf) passes

    PIPE_ISSUE(0, 0);
    PIPE_ISSUE(1, 1);

    #pragma unroll 1
    for (int s = 0; s < NSTG; s++) {
        int st = s % 3;
        if (s + 2 < NSTG) PIPE_ISSUE(s + 2, (s + 2) % 3);

        if (s < NSTG - 2)       asm volatile("cp.async.wait_group 2;" ::: "memory");
        else if (s == NSTG - 2) asm volatile("cp.async.wait_group 1;" ::: "memory");
        else                    asm volatile("cp.async.wait_group 0;" ::: "memory");

        const char* cb = my_smem + st * STG_BYTES;
        longlong2 a0 = *(const longlong2*)(cb + 0);
        longlong2 a1 = *(const longlong2*)(cb + 128);
        longlong2 c0 = *(const longlong2*)(cb + 256);
        longlong2 c1 = *(const longlong2*)(cb + 384);

        float s0 = row_dist(a0, a1, nq0, nq1, nq2, nq3);
        float s1 = row_dist(c0, c1, nq0, nq1, nq2, nq3);

        int m0 = row0 + (s << 6) + G;          // mask bits 2s, 2s+1
        if (mk != 0u) {
            if ((mk >> (2 * s)) & 1u)     s0 = g_drv[b * Rr + g_flag[m0]];
            if ((mk >> (2 * s + 1)) & 1u) s1 = g_drv[b * Rr + g_flag[m0 + 32]];
        }

        if (!(s0 > tf)) {                      // rare insert (group-uniform)
            u64 cand = ((u64)__float_as_uint(s0) << 32) | (unsigned)m0;
            if (cand < thresh) {
                u64 vprev = __shfl_up_sync(gmask, v, 1, 8);
                if (cand < v) v = ((lir != 0) && (cand < vprev)) ? vprev : cand;
                thresh = __shfl_sync(gmask, v, 7, 8);
                tf = __uint_as_float((unsigned)(thresh >> 32));
            }
        }
        if (!(s1 > tf)) {
            u64 cand = ((u64)__float_as_uint(s1) << 32) | (unsigned)(m0 + 32);
            if (cand < thresh) {
                u64 vprev = __shfl_up_sync(gmask, v, 1, 8);
                if (cand < v) v = ((lir != 0) && (cand < vprev)) ? vprev : cand;
                thresh = __shfl_sync(gmask, v, 7, 8);
                tf = __uint_as_float((unsigned)(thresh >> 32));
            }
        }
    }

    // block merge: each lane writes its rank-lir value; 32 groups x 8 sorted asc
    __shared__ u64 s_c[32 * Kk];
    s_c[G * Kk + lir] = v;
    __syncthreads();

    if (warp == 0) {
        u64 vv[Kk];
        #pragma unroll
        for (int i = 0; i < Kk; i++) vv[i] = s_c[lane * Kk + i];   // sorted asc per lane

        u64* outc = g_cand + ((size_t)b * NBLK + blockIdx.x) * Kk;
        #pragma unroll 1
        for (int r = 0; r < Kk; r++) {
            u64 my = vv[0];
            u64 g = my;
            #pragma unroll
            for (int off = 16; off; off >>= 1) {
                u64 o = __shfl_xor_sync(0xffffffffu, g, off);
                if (o < g) g = o;
            }
            if (g == my) {
                #pragma unroll
                for (int i = 0; i < Kk - 1; i++) vv[i] = vv[i + 1];
                vv[Kk - 1] = ULLMAX;
            }
            if (lane == 0) outc[r] = g;
        }
    }

    // ---- last-block-per-batch fused finalize (threadfence-reduction pattern) ----
    __shared__ int s_last;
    if (t == 0) {
        __threadfence();                       // publish this block's g_cand
        unsigned old = atomicAdd(&g_cnt[b], 1u);
        s_last = (old == NBLK - 1);
        __threadfence();                       // acquire other blocks' g_cand
    }
    __syncthreads();
    if (!s_last) return;

    __shared__ u64   s_sel[Kk];
    __shared__ int   s_pos[Rr];
    __shared__ float s_nd[Rr];

    if (t < 32) {
        const u64* cb2 = g_cand + (size_t)b * NBLK * Kk;
        u64 fb[Kk];
        #pragma unroll
        for (int i = 0; i < Kk; i++) fb[i] = ULLMAX;
        #pragma unroll
        for (int i = 0; i < 16; i++) insert_cand(fb, cb2[lane * 16 + i]);
        #pragma unroll 1
        for (int r = 0; r < Kk; r++) {
            u64 my = fb[0];
            u64 g = my;
            #pragma unroll
            for (int off = 16; off; off >>= 1) {
                u64 o = __shfl_xor_sync(0xffffffffu, g, off);
                if (o < g) g = o;
            }
            if (g == my) {
                #pragma unroll
                for (int j = 0; j < Kk - 1; j++) fb[j] = fb[j + 1];
                fb[Kk - 1] = ULLMAX;
            }
            if (lane == 0) s_sel[r] = g;
        }
    }
    __syncthreads();

    if (t < Rr) {
        float d_t = (t < Kk) ? __uint_as_float((unsigned)(s_sel[t] >> 32)) : 0.0f;
        int   p_t = (t < Kk) ? (int)(unsigned)(s_sel[t] & 0xFFFFFFFFu) : last_used[b];
        float maxd = 0.0f;
        #pragma unroll
        for (int i = 0; i < Kk; i++) {
            float di = __uint_as_float((unsigned)(s_sel[i] >> 32));
            if (di > maxd) maxd = di;
        }
        s_pos[t] = p_t;
        s_nd[t]  = d_t / maxd;
        out[OUT1_OFF + b * Rr + t] = s_nd[t];
    }
    __syncthreads();

    // gather 9 rows (mask-aware: scattered rows come from rv)
    for (int i = t; i < Rr * Wc; i += 256) {
        int k = i >> 6, w = i & 63;
        int m = s_pos[k];
        unsigned mw = g_mask[(m >> 10) * 32 + (m & 31)];
        int f = ((mw >> ((m >> 5) & 31)) & 1u) ? g_flag[m] : -1;
        float val = (f >= 0) ? g_rv[b * Rr * Wc + f * Wc + w]
                             : sparse[((size_t)b * Mrows + m) * Wc + w];
        out[OUT2_OFF + b * Rr * Wc + i] = val;
        if (k < Kk) out[OUT0_OFF + b * Kk * Wc + k * Wc + w] = val;
    }
}

// ---------------- launch ----------------
extern "C" void kernel_launch(void* const* d_in, const int* in_sizes, int n_in,
                              void* d_out, int out_size) {
    const float* xi            = (const float*)d_in[0];
    const float* sparse        = (const float*)d_in[1];
    const float* read_weights  = (const float*)d_in[2];
    const float* read_vectors  = (const float*)d_in[3];
    const float* W             = (const float*)d_in[4];
    const float* bias          = (const float*)d_in[5];
    const int*   read_positions= (const int*)d_in[6];
    const int*   last_used     = (const int*)d_in[7];
    float* out = (float*)d_out;

    // static + dynamic smem in k_dist exceeds the 48 KB default pool;
    // opt in (host-side attribute set: no alloc, no sync, capture-safe, idempotent)
    cudaFuncSetAttribute((const void*)k_dist,
                         cudaFuncAttributeMaxDynamicSharedMemorySize,
                         3 * STG_BYTES);

    k_setup<<<Bsz + 1, 256>>>(xi, W, bias, read_weights, read_vectors, read_positions);
    k_dist<<<dim3(NBLK, Bsz), 256, 3 * STG_BYTES>>>(sparse, last_used, out);
}